// round 3
// baseline (speedup 1.0000x reference)
#include <cuda_runtime.h>
#include <math.h>

#define CDIV(a,b) (((a)+(b)-1)/(b))

constexpr int DMODEL = 900;
constexpr int DSTATE = 16;
constexpr int DINNER = 1800;
constexpr int DTRANK = 57;
constexpr int BSZ    = 2;
constexpr int SEQL   = 900;
constexpr int MROWS  = BSZ * SEQL;          // 1800
constexpr int DXP    = DTRANK + 2 * DSTATE; // 89

// ---------------- scratch (static device globals; no allocation) ----------
__device__ float g_x     [MROWS * DMODEL];      // emb + pe (residual)
__device__ float g_xn    [MROWS * DMODEL];      // rmsnorm(x); reused for W_out output
__device__ float g_xr    [MROWS * 2 * DINNER];  // W_in output
__device__ float g_xm    [MROWS * DINNER];      // fwd conv+silu
__device__ float g_xb    [MROWS * DINNER];      // bwd (channel-reversed) conv+silu
__device__ float g_xd0   [MROWS * DXP];
__device__ float g_xd1   [MROWS * DXP];
__device__ float g_delta0[MROWS * DINNER];
__device__ float g_delta1[MROWS * DINNER];
__device__ float g_y0    [MROWS * DINNER];
__device__ float g_y1    [MROWS * DINNER];
__device__ float g_comb  [MROWS * DINNER];

__device__ __forceinline__ float siluf(float x) { return x / (1.f + __expf(-x)); }

// ---------------- GEMM: C[M,N] = A[M,K] @ W[N,K]^T, fused epilogues -------
// EPI 0: none. EPI 1: (acc + bias[col])*30 + pe[(row%L)*DMODEL + col].
// EPI 2: softplus(acc + bias[col]).
template<int EPI>
__global__ __launch_bounds__(256, 2) void gemm_nt(
    const float* __restrict__ A, int lda,
    const float* __restrict__ W, int ldw,
    const float* __restrict__ bias,
    const float* __restrict__ pe,
    float* __restrict__ C, int ldc,
    int M, int N, int K)
{
    __shared__ float As[8][132];
    __shared__ float Bs[8][132];
    const int t   = threadIdx.x;
    const int bm  = blockIdx.y * 128;
    const int bn  = blockIdx.x * 128;
    const int lrow = t >> 1;           // 0..127
    const int lk4  = (t & 1) << 2;     // 0 or 4
    const int tx  = t & 15;
    const int ty  = t >> 4;

    float acc[8][8];
#pragma unroll
    for (int i = 0; i < 8; i++)
#pragma unroll
        for (int j = 0; j < 8; j++) acc[i][j] = 0.f;

    const int arow = bm + lrow;
    const int brow = bn + lrow;
    const float* Aptr = A + (long)arow * lda;
    const float* Wptr = W + (long)brow * ldw;
    const bool aok = (arow < M);
    const bool bok = (brow < N);

    for (int k0 = 0; k0 < K; k0 += 8) {
#pragma unroll
        for (int i = 0; i < 4; i++) {
            int kk = k0 + lk4 + i;
            As[lk4 + i][lrow] = (aok && kk < K) ? Aptr[kk] : 0.f;
            Bs[lk4 + i][lrow] = (bok && kk < K) ? Wptr[kk] : 0.f;
        }
        __syncthreads();
#pragma unroll
        for (int kk = 0; kk < 8; kk++) {
            float4 a0 = *(const float4*)&As[kk][ty * 8];
            float4 a1 = *(const float4*)&As[kk][ty * 8 + 4];
            float4 b0 = *(const float4*)&Bs[kk][tx * 8];
            float4 b1 = *(const float4*)&Bs[kk][tx * 8 + 4];
            float av[8] = {a0.x, a0.y, a0.z, a0.w, a1.x, a1.y, a1.z, a1.w};
            float bv[8] = {b0.x, b0.y, b0.z, b0.w, b1.x, b1.y, b1.z, b1.w};
#pragma unroll
            for (int i = 0; i < 8; i++)
#pragma unroll
                for (int j = 0; j < 8; j++)
                    acc[i][j] = fmaf(av[i], bv[j], acc[i][j]);
        }
        __syncthreads();
    }

#pragma unroll
    for (int i = 0; i < 8; i++) {
        int row = bm + ty * 8 + i;
        if (row < M) {
#pragma unroll
            for (int j = 0; j < 8; j++) {
                int col = bn + tx * 8 + j;
                if (col < N) {
                    float v = acc[i][j];
                    if (EPI == 1) {
                        v = (v + bias[col]) * 30.0f + pe[(long)(row % SEQL) * DMODEL + col];
                    } else if (EPI == 2) {
                        v += bias[col];
                        v = (v > 20.f) ? v : log1pf(expf(v));
                    }
                    C[(long)row * ldc + col] = v;
                }
            }
        }
    }
}

// ---------------- RMSNorm (optionally fused residual add) -----------------
__global__ void rmsnorm_kernel(const float* __restrict__ in,
                               const float* __restrict__ res,  // nullable
                               const float* __restrict__ w,
                               float* __restrict__ out, int D)
{
    int row = blockIdx.x;
    const float* x = in + (long)row * D;
    const float* r = res ? res + (long)row * D : nullptr;
    float s = 0.f;
    for (int i = threadIdx.x; i < D; i += blockDim.x) {
        float v = x[i] + (r ? r[i] : 0.f);
        s += v * v;
    }
    __shared__ float red[32];
#pragma unroll
    for (int o = 16; o; o >>= 1) s += __shfl_xor_sync(0xffffffff, s, o);
    int wid = threadIdx.x >> 5, lid = threadIdx.x & 31;
    if (lid == 0) red[wid] = s;
    __syncthreads();
    if (wid == 0) {
        s = (lid < (int)(blockDim.x >> 5)) ? red[lid] : 0.f;
#pragma unroll
        for (int o = 16; o; o >>= 1) s += __shfl_xor_sync(0xffffffff, s, o);
        if (lid == 0) red[0] = s;
    }
    __syncthreads();
    float scale = rsqrtf(red[0] / (float)D + 1e-5f);
    for (int i = threadIdx.x; i < D; i += blockDim.x) {
        float v = x[i] + (r ? r[i] : 0.f);
        out[(long)row * D + i] = v * scale * w[i];
    }
}

// ---------------- causal depthwise conv(4) + SiLU, fwd + channel-reversed -
__global__ void conv_silu_kernel(const float* __restrict__ cw,
                                 const float* __restrict__ cb)
{
    long idx = (long)blockIdx.x * blockDim.x + threadIdx.x;
    if (idx >= (long)MROWS * DINNER) return;
    int d  = (int)(idx % DINNER);
    long bl = idx / DINNER;
    int l  = (int)(bl % SEQL);
    long bbase = (bl - l) * (2L * DINNER);   // (b*SEQL) * 3600
    int db = DINNER - 1 - d;
    float accf = cb[d], accb = cb[d];
#pragma unroll
    for (int j = 0; j < 4; j++) {
        int ls = l - 3 + j;
        if (ls >= 0) {
            float wj = cw[d * 4 + j];
            const float* rowp = g_xr + bbase + (long)ls * (2 * DINNER);
            accf = fmaf(wj, rowp[d],  accf);
            accb = fmaf(wj, rowp[db], accb);
        }
    }
    g_xm[idx] = siluf(accf);
    g_xb[idx] = siluf(accb);
}

// ---------------- selective scan, both directions in one launch -----------
// 1 thread per (dir, b, d); 16 states in registers; B/C staged in smem.
constexpr int SCAN_CHUNK = 36;  // 900 / 36 = 25 chunks
__global__ __launch_bounds__(128) void scan_kernel(
    const float* __restrict__ A_log, const float* __restrict__ Dv)
{
    __shared__ float sBC[SCAN_CHUNK][32];  // [l][0:16]=B, [16:32]=C
    int bidx = blockIdx.x;
    int dir  = bidx / (BSZ * 15);
    int rem  = bidx % (BSZ * 15);
    int b    = rem / 15;
    int d    = (rem % 15) * 128 + threadIdx.x;
    bool active = d < DINNER;

    const float* u  = (dir ? g_xb     : g_xm)     + (long)b * SEQL * DINNER;
    const float* dl = (dir ? g_delta1 : g_delta0) + (long)b * SEQL * DINNER;
    const float* xd = (dir ? g_xd1    : g_xd0)    + (long)b * SEQL * DXP;
    float*       y  = (dir ? g_y1     : g_y0)     + (long)b * SEQL * DINNER;

    float An[DSTATE];
    float Dd = 0.f, h[DSTATE];
    if (active) {
#pragma unroll
        for (int n = 0; n < DSTATE; n++) An[n] = -expf(A_log[(long)d * DSTATE + n]);
        Dd = Dv[d];
    }
#pragma unroll
    for (int n = 0; n < DSTATE; n++) h[n] = 0.f;

    for (int l0 = 0; l0 < SEQL; l0 += SCAN_CHUNK) {
        __syncthreads();
        for (int i = threadIdx.x; i < SCAN_CHUNK * 32; i += 128) {
            int li = i >> 5, c = i & 31;
            sBC[li][c] = xd[(long)(l0 + li) * DXP + DTRANK + c];
        }
        __syncthreads();
        if (active) {
            for (int li = 0; li < SCAN_CHUNK; li++) {
                long l = l0 + li;
                float dlt = dl[l * DINNER + d];
                float uu  = u [l * DINNER + d];
                float du  = dlt * uu;
                float yv  = 0.f;
#pragma unroll
                for (int n = 0; n < DSTATE; n++) {
                    float dA = __expf(dlt * An[n]);
                    h[n] = fmaf(dA, h[n], du * sBC[li][n]);
                    yv   = fmaf(h[n], sBC[li][16 + n], yv);
                }
                y[l * DINNER + d] = fmaf(uu, Dd, yv);
            }
        }
    }
}

// ---------------- combine: (y_f + rev(y_b)) * silu(res) -------------------
__global__ void combine_kernel()
{
    long idx = (long)blockIdx.x * blockDim.x + threadIdx.x;
    if (idx >= (long)MROWS * DINNER) return;
    int d   = (int)(idx % DINNER);
    long bl = idx / DINNER;
    float yf  = g_y0[idx];
    float yb  = g_y1[bl * DINNER + (DINNER - 1 - d)];
    float res = g_xr[bl * (2L * DINNER) + DINNER + d];
    float g   = res / (1.f + __expf(-res));
    g_comb[idx] = (yf + yb) * g;
}

// ---------------- launch ---------------------------------------------------
extern "C" void kernel_launch(void* const* d_in, const int* in_sizes, int n_in,
                              void* d_out, int out_size)
{
    const float* inp     = (const float*)d_in[0];
    const float* W_emb   = (const float*)d_in[1];
    const float* b_emb   = (const float*)d_in[2];
    const float* norm_w  = (const float*)d_in[3];
    const float* W_in    = (const float*)d_in[4];
    const float* conv_w  = (const float*)d_in[5];
    const float* conv_b  = (const float*)d_in[6];
    const float* W_xp    = (const float*)d_in[7];
    const float* W_dt    = (const float*)d_in[8];
    const float* b_dt    = (const float*)d_in[9];
    const float* A_log   = (const float*)d_in[10];
    const float* Dv      = (const float*)d_in[11];
    const float* W_out   = (const float*)d_in[12];
    const float* normf_w = (const float*)d_in[13];
    const float* pe      = (const float*)d_in[14];
    float* out = (float*)d_out;

    void *px, *pxn, *pxr, *pxm, *pxb, *pxd0, *pxd1, *pd0, *pd1, *pcomb;
    cudaGetSymbolAddress(&px,    g_x);
    cudaGetSymbolAddress(&pxn,   g_xn);
    cudaGetSymbolAddress(&pxr,   g_xr);
    cudaGetSymbolAddress(&pxm,   g_xm);
    cudaGetSymbolAddress(&pxb,   g_xb);
    cudaGetSymbolAddress(&pxd0,  g_xd0);
    cudaGetSymbolAddress(&pxd1,  g_xd1);
    cudaGetSymbolAddress(&pd0,   g_delta0);
    cudaGetSymbolAddress(&pd1,   g_delta1);
    cudaGetSymbolAddress(&pcomb, g_comb);

    const int MT = CDIV(MROWS, 128);  // 15 row tiles

    // 1. x = (inp @ W_emb^T + b_emb) * sqrt(900) + pe
    gemm_nt<1><<<dim3(CDIV(DMODEL, 128), MT), 256>>>(
        inp, DMODEL, W_emb, DMODEL, b_emb, pe, (float*)px, DMODEL,
        MROWS, DMODEL, DMODEL);

    // 2. xn = rmsnorm(x, norm_w)
    rmsnorm_kernel<<<MROWS, 256>>>((const float*)px, nullptr, norm_w,
                                   (float*)pxn, DMODEL);

    // 3. xr = xn @ W_in^T  (N = 3600)
    gemm_nt<0><<<dim3(CDIV(2 * DINNER, 128), MT), 256>>>(
        (const float*)pxn, DMODEL, W_in, DMODEL, nullptr, nullptr,
        (float*)pxr, 2 * DINNER, MROWS, 2 * DINNER, DMODEL);

    // 4. depthwise causal conv + silu (fwd + channel-reversed)
    conv_silu_kernel<<<CDIV((long)MROWS * DINNER, 256), 256>>>(conv_w, conv_b);

    // 5. xd = u @ W_xp^T for both directions (N = 89)
    gemm_nt<0><<<dim3(1, MT), 256>>>(
        (const float*)pxm, DINNER, W_xp, DINNER, nullptr, nullptr,
        (float*)pxd0, DXP, MROWS, DXP, DINNER);
    gemm_nt<0><<<dim3(1, MT), 256>>>(
        (const float*)pxb, DINNER, W_xp, DINNER, nullptr, nullptr,
        (float*)pxd1, DXP, MROWS, DXP, DINNER);

    // 6. delta = softplus(xd[:, :57] @ W_dt^T + b_dt)
    gemm_nt<2><<<dim3(CDIV(DINNER, 128), MT), 256>>>(
        (const float*)pxd0, DXP, W_dt, DTRANK, b_dt, nullptr,
        (float*)pd0, DINNER, MROWS, DINNER, DTRANK);
    gemm_nt<2><<<dim3(CDIV(DINNER, 128), MT), 256>>>(
        (const float*)pxd1, DXP, W_dt, DTRANK, b_dt, nullptr,
        (float*)pd1, DINNER, MROWS, DINNER, DTRANK);

    // 7. selective scan, both directions
    scan_kernel<<<2 * BSZ * 15, 128>>>(A_log, Dv);

    // 8. combine with gate
    combine_kernel<<<CDIV((long)MROWS * DINNER, 256), 256>>>();

    // 9. mamba_out = comb @ W_out^T  (reuse g_xn)
    gemm_nt<0><<<dim3(CDIV(DMODEL, 128), MT), 256>>>(
        (const float*)pcomb, DINNER, W_out, DINNER, nullptr, nullptr,
        (float*)pxn, DMODEL, MROWS, DMODEL, DINNER);

    // 10. out = rmsnorm(mamba_out + x, normf_w)
    rmsnorm_kernel<<<MROWS, 256>>>((const float*)pxn, (const float*)px,
                                   normf_w, out, DMODEL);
}

// round 4
// speedup vs baseline: 1.8943x; 1.8943x over previous
#include <cuda_runtime.h>
#include <math.h>
#include <stdint.h>

#define CDIV(a,b) (((a)+(b)-1)/(b))

constexpr int DMODEL = 900;
constexpr int DSTATE = 16;
constexpr int DINNER = 1800;
constexpr int DTRANK = 57;
constexpr int BSZ    = 2;
constexpr int SEQL   = 900;
constexpr int MROWS  = BSZ * SEQL;          // 1800
constexpr int DXP    = DTRANK + 2 * DSTATE; // 89

// ---------------- scratch (static device globals; no allocation) ----------
__device__ float g_x     [MROWS * DMODEL];
__device__ float g_xn    [MROWS * DMODEL];
__device__ float g_xr    [MROWS * 2 * DINNER];
__device__ float g_xm    [MROWS * DINNER];
__device__ float g_xb    [MROWS * DINNER];
__device__ float g_xd0   [MROWS * DXP];
__device__ float g_xd1   [MROWS * DXP];
__device__ float g_delta0[MROWS * DINNER];
__device__ float g_delta1[MROWS * DINNER];
__device__ float g_y0    [MROWS * DINNER];
__device__ float g_y1    [MROWS * DINNER];
__device__ float g_comb  [MROWS * DINNER];

__device__ __forceinline__ float siluf(float x) { return x / (1.f + __expf(-x)); }

// ---------------- tf32 helpers --------------------------------------------
__device__ __forceinline__ uint32_t f2tf32(float x) {
    uint32_t r;
    asm("cvt.rna.tf32.f32 %0, %1;" : "=r"(r) : "f"(x));
    return r;
}
__device__ __forceinline__ void tf32split(float x, uint32_t& hi, uint32_t& lo) {
    hi = f2tf32(x);
    lo = f2tf32(x - __uint_as_float(hi));
}
__device__ __forceinline__ void mma8(float* c, const uint32_t* a, const uint32_t* b) {
    asm volatile(
        "mma.sync.aligned.m16n8k8.row.col.f32.tf32.tf32.f32 "
        "{%0,%1,%2,%3},{%4,%5,%6,%7},{%8,%9},{%0,%1,%2,%3};"
        : "+f"(c[0]), "+f"(c[1]), "+f"(c[2]), "+f"(c[3])
        : "r"(a[0]), "r"(a[1]), "r"(a[2]), "r"(a[3]), "r"(b[0]), "r"(b[1]));
}

// ---------------- tensor-core GEMM: C[M,N] = A[M,K] @ W[N,K]^T -------------
// 3xTF32 (hi/lo split of both operands) for ~fp32 accuracy.
// EPI 0: none. EPI 1: (acc+bias[col])*30 + pe[(row%L)*DMODEL+col].
// EPI 2: softplus(acc+bias[col]).  SPLITK: atomicAdd into C (EPI ignored).
// blockIdx.z encodes (dir, ksplit): dir = z / nsplit (selects A0/C0 vs A1/C1).
template<int EPI, bool SPLITK>
__global__ __launch_bounds__(256) void gemm_tc(
    const float* __restrict__ A0, const float* __restrict__ A1, int lda,
    const float* __restrict__ W, int ldw,
    const float* __restrict__ bias, const float* __restrict__ pe,
    float* __restrict__ C0, float* __restrict__ C1, int ldc,
    int M, int N, int K, int nsplit)
{
    __shared__ float As[2][128][20];
    __shared__ float Bs[2][128][20];

    const int tid  = threadIdx.x;
    const int lane = tid & 31;
    const int wid  = tid >> 5;
    const int g    = lane >> 2;
    const int tg   = lane & 3;
    const int wm0  = (wid & 3) * 32;
    const int wn0  = (wid >> 2) * 64;
    const int bm   = blockIdx.y * 128;
    const int bn   = blockIdx.x * 128;

    const int dir = blockIdx.z / nsplit;
    const int ks  = blockIdx.z % nsplit;
    const float* A = dir ? A1 : A0;
    float*       C = dir ? C1 : C0;

    const int Kc   = (K + nsplit - 1) / nsplit;
    const int kbeg = ks * Kc;
    const int kend = min(K, kbeg + Kc);
    const int nst  = (kend > kbeg) ? ((kend - kbeg + 15) >> 4) : 0;
    if (nst == 0) return;

    float acc[2][8][4];
#pragma unroll
    for (int mt = 0; mt < 2; mt++)
#pragma unroll
        for (int nt = 0; nt < 8; nt++)
#pragma unroll
            for (int i = 0; i < 4; i++) acc[mt][nt][i] = 0.f;

    float ra[8], rb[8];
    auto ldg_stage = [&](int kb) {
#pragma unroll
        for (int i = 0; i < 8; i++) {
            int id = i * 256 + tid;
            int m = id >> 4, k = id & 15;
            int gk = kb + k;
            ra[i] = (bm + m < M && gk < kend) ? A[(long)(bm + m) * lda + gk] : 0.f;
            rb[i] = (bn + m < N && gk < kend) ? W[(long)(bn + m) * ldw + gk] : 0.f;
        }
    };
    auto sts_stage = [&](int buf) {
#pragma unroll
        for (int i = 0; i < 8; i++) {
            int id = i * 256 + tid;
            int m = id >> 4, k = id & 15;
            As[buf][m][k] = ra[i];
            Bs[buf][m][k] = rb[i];
        }
    };

    ldg_stage(kbeg);
    sts_stage(0);
    __syncthreads();

    for (int s = 0; s < nst; s++) {
        const int cur = s & 1;
        if (s + 1 < nst) ldg_stage(kbeg + (s + 1) * 16);

#pragma unroll
        for (int half = 0; half < 2; half++) {
            const int kk = half * 8;
            uint32_t bhi[8][2], blo[8][2];
#pragma unroll
            for (int nt = 0; nt < 8; nt++) {
                int rn = wn0 + nt * 8 + g;
                float b0 = Bs[cur][rn][kk + tg];
                float b1 = Bs[cur][rn][kk + tg + 4];
                tf32split(b0, bhi[nt][0], blo[nt][0]);
                tf32split(b1, bhi[nt][1], blo[nt][1]);
            }
#pragma unroll
            for (int mt = 0; mt < 2; mt++) {
                int rm = wm0 + mt * 16 + g;
                float a0 = As[cur][rm    ][kk + tg];
                float a1 = As[cur][rm + 8][kk + tg];
                float a2 = As[cur][rm    ][kk + tg + 4];
                float a3 = As[cur][rm + 8][kk + tg + 4];
                uint32_t ahi[4], alo[4];
                tf32split(a0, ahi[0], alo[0]);
                tf32split(a1, ahi[1], alo[1]);
                tf32split(a2, ahi[2], alo[2]);
                tf32split(a3, ahi[3], alo[3]);
#pragma unroll
                for (int nt = 0; nt < 8; nt++) {
                    mma8(acc[mt][nt], ahi, bhi[nt]);
                    mma8(acc[mt][nt], alo, bhi[nt]);
                    mma8(acc[mt][nt], ahi, blo[nt]);
                }
            }
        }

        if (s + 1 < nst) sts_stage((s + 1) & 1);
        __syncthreads();
    }

#pragma unroll
    for (int mt = 0; mt < 2; mt++)
#pragma unroll
        for (int nt = 0; nt < 8; nt++)
#pragma unroll
            for (int i = 0; i < 4; i++) {
                int row = bm + wm0 + mt * 16 + g + (i >> 1) * 8;
                int col = bn + wn0 + nt * 8 + 2 * tg + (i & 1);
                if (row < M && col < N) {
                    float v = acc[mt][nt][i];
                    if (SPLITK) {
                        atomicAdd(&C[(long)row * ldc + col], v);
                    } else {
                        if (EPI == 1) {
                            v = (v + bias[col]) * 30.0f + pe[(long)(row % SEQL) * DMODEL + col];
                        } else if (EPI == 2) {
                            v += bias[col];
                            v = (v > 20.f) ? v : log1pf(expf(v));
                        }
                        C[(long)row * ldc + col] = v;
                    }
                }
            }
}

// ---------------- RMSNorm (optionally fused residual add) -----------------
__global__ void rmsnorm_kernel(const float* __restrict__ in,
                               const float* __restrict__ res,
                               const float* __restrict__ w,
                               float* __restrict__ out, int D)
{
    int row = blockIdx.x;
    const float* x = in + (long)row * D;
    const float* r = res ? res + (long)row * D : nullptr;
    float s = 0.f;
    for (int i = threadIdx.x; i < D; i += blockDim.x) {
        float v = x[i] + (r ? r[i] : 0.f);
        s += v * v;
    }
    __shared__ float red[32];
#pragma unroll
    for (int o = 16; o; o >>= 1) s += __shfl_xor_sync(0xffffffff, s, o);
    int wid = threadIdx.x >> 5, lid = threadIdx.x & 31;
    if (lid == 0) red[wid] = s;
    __syncthreads();
    if (wid == 0) {
        s = (lid < (int)(blockDim.x >> 5)) ? red[lid] : 0.f;
#pragma unroll
        for (int o = 16; o; o >>= 1) s += __shfl_xor_sync(0xffffffff, s, o);
        if (lid == 0) red[0] = s;
    }
    __syncthreads();
    float scale = rsqrtf(red[0] / (float)D + 1e-5f);
    for (int i = threadIdx.x; i < D; i += blockDim.x) {
        float v = x[i] + (r ? r[i] : 0.f);
        out[(long)row * D + i] = v * scale * w[i];
    }
}

// ---------------- causal depthwise conv(4) + SiLU, fwd + channel-reversed -
__global__ void conv_silu_kernel(const float* __restrict__ cw,
                                 const float* __restrict__ cb)
{
    long idx = (long)blockIdx.x * blockDim.x + threadIdx.x;
    if (idx >= (long)MROWS * DINNER) return;
    int d  = (int)(idx % DINNER);
    long bl = idx / DINNER;
    int l  = (int)(bl % SEQL);
    long bbase = (bl - l) * (2L * DINNER);
    int db = DINNER - 1 - d;
    float accf = cb[d], accb = cb[d];
#pragma unroll
    for (int j = 0; j < 4; j++) {
        int ls = l - 3 + j;
        if (ls >= 0) {
            float wj = cw[d * 4 + j];
            const float* rowp = g_xr + bbase + (long)ls * (2 * DINNER);
            accf = fmaf(wj, rowp[d],  accf);
            accb = fmaf(wj, rowp[db], accb);
        }
    }
    g_xm[idx] = siluf(accf);
    g_xb[idx] = siluf(accb);
}

// ---------------- selective scan, both directions in one launch -----------
constexpr int SCAN_CHUNK = 36;
__global__ __launch_bounds__(128) void scan_kernel(
    const float* __restrict__ A_log, const float* __restrict__ Dv)
{
    __shared__ float sBC[SCAN_CHUNK][32];
    int bidx = blockIdx.x;
    int dir  = bidx / (BSZ * 15);
    int rem  = bidx % (BSZ * 15);
    int b    = rem / 15;
    int d    = (rem % 15) * 128 + threadIdx.x;
    bool active = d < DINNER;

    const float* u  = (dir ? g_xb     : g_xm)     + (long)b * SEQL * DINNER;
    const float* dl = (dir ? g_delta1 : g_delta0) + (long)b * SEQL * DINNER;
    const float* xd = (dir ? g_xd1    : g_xd0)    + (long)b * SEQL * DXP;
    float*       y  = (dir ? g_y1     : g_y0)     + (long)b * SEQL * DINNER;

    float An[DSTATE];
    float Dd = 0.f, h[DSTATE];
    if (active) {
#pragma unroll
        for (int n = 0; n < DSTATE; n++) An[n] = -expf(A_log[(long)d * DSTATE + n]);
        Dd = Dv[d];
    }
#pragma unroll
    for (int n = 0; n < DSTATE; n++) h[n] = 0.f;

    for (int l0 = 0; l0 < SEQL; l0 += SCAN_CHUNK) {
        __syncthreads();
        for (int i = threadIdx.x; i < SCAN_CHUNK * 32; i += 128) {
            int li = i >> 5, c = i & 31;
            sBC[li][c] = xd[(long)(l0 + li) * DXP + DTRANK + c];
        }
        __syncthreads();
        if (active) {
            for (int li = 0; li < SCAN_CHUNK; li++) {
                long l = l0 + li;
                float dlt = dl[l * DINNER + d];
                float uu  = u [l * DINNER + d];
                float du  = dlt * uu;
                float yv  = 0.f;
#pragma unroll
                for (int n = 0; n < DSTATE; n++) {
                    float dA = __expf(dlt * An[n]);
                    h[n] = fmaf(dA, h[n], du * sBC[li][n]);
                    yv   = fmaf(h[n], sBC[li][16 + n], yv);
                }
                y[l * DINNER + d] = fmaf(uu, Dd, yv);
            }
        }
    }
}

// ---------------- combine: (y_f + rev(y_b)) * silu(res) -------------------
__global__ void combine_kernel()
{
    long idx = (long)blockIdx.x * blockDim.x + threadIdx.x;
    if (idx >= (long)MROWS * DINNER) return;
    int d   = (int)(idx % DINNER);
    long bl = idx / DINNER;
    float yf  = g_y0[idx];
    float yb  = g_y1[bl * DINNER + (DINNER - 1 - d)];
    float res = g_xr[bl * (2L * DINNER) + DINNER + d];
    float g   = res / (1.f + __expf(-res));
    g_comb[idx] = (yf + yb) * g;
}

// ---------------- launch ---------------------------------------------------
extern "C" void kernel_launch(void* const* d_in, const int* in_sizes, int n_in,
                              void* d_out, int out_size)
{
    const float* inp     = (const float*)d_in[0];
    const float* W_emb   = (const float*)d_in[1];
    const float* b_emb   = (const float*)d_in[2];
    const float* norm_w  = (const float*)d_in[3];
    const float* W_in    = (const float*)d_in[4];
    const float* conv_w  = (const float*)d_in[5];
    const float* conv_b  = (const float*)d_in[6];
    const float* W_xp    = (const float*)d_in[7];
    const float* W_dt    = (const float*)d_in[8];
    const float* b_dt    = (const float*)d_in[9];
    const float* A_log   = (const float*)d_in[10];
    const float* Dv      = (const float*)d_in[11];
    const float* W_out   = (const float*)d_in[12];
    const float* normf_w = (const float*)d_in[13];
    const float* pe      = (const float*)d_in[14];
    float* out = (float*)d_out;

    void *px, *pxn, *pxr, *pxm, *pxb, *pxd0, *pxd1, *pd0, *pd1, *pcomb;
    cudaGetSymbolAddress(&px,    g_x);
    cudaGetSymbolAddress(&pxn,   g_xn);
    cudaGetSymbolAddress(&pxr,   g_xr);
    cudaGetSymbolAddress(&pxm,   g_xm);
    cudaGetSymbolAddress(&pxb,   g_xb);
    cudaGetSymbolAddress(&pxd0,  g_xd0);
    cudaGetSymbolAddress(&pxd1,  g_xd1);
    cudaGetSymbolAddress(&pd0,   g_delta0);
    cudaGetSymbolAddress(&pd1,   g_delta1);
    cudaGetSymbolAddress(&pcomb, g_comb);

    const int MT = CDIV(MROWS, 128);   // 15
    const int KS = 5;                  // split-K for the skinny W_xp GEMM

    // 1. x = (inp @ W_emb^T + b_emb) * sqrt(900) + pe
    gemm_tc<1, false><<<dim3(CDIV(DMODEL, 128), MT, 1), 256>>>(
        inp, nullptr, DMODEL, W_emb, DMODEL, b_emb, pe,
        (float*)px, nullptr, DMODEL, MROWS, DMODEL, DMODEL, 1);

    // 2. xn = rmsnorm(x, norm_w)
    rmsnorm_kernel<<<MROWS, 256>>>((const float*)px, nullptr, norm_w,
                                   (float*)pxn, DMODEL);

    // 3. xr = xn @ W_in^T  (N = 3600)
    gemm_tc<0, false><<<dim3(CDIV(2 * DINNER, 128), MT, 1), 256>>>(
        (const float*)pxn, nullptr, DMODEL, W_in, DMODEL, nullptr, nullptr,
        (float*)pxr, nullptr, 2 * DINNER, MROWS, 2 * DINNER, DMODEL, 1);

    // 4. depthwise causal conv + silu (fwd + channel-reversed)
    conv_silu_kernel<<<CDIV((long)MROWS * DINNER, 256), 256>>>(conv_w, conv_b);

    // 5. xd = u @ W_xp^T for both directions (N = 89), split-K + atomics
    cudaMemsetAsync(pxd0, 0, (size_t)MROWS * DXP * sizeof(float), 0);
    cudaMemsetAsync(pxd1, 0, (size_t)MROWS * DXP * sizeof(float), 0);
    gemm_tc<0, true><<<dim3(1, MT, 2 * KS), 256>>>(
        (const float*)pxm, (const float*)pxb, DINNER, W_xp, DINNER,
        nullptr, nullptr, (float*)pxd0, (float*)pxd1, DXP,
        MROWS, DXP, DINNER, KS);

    // 6. delta = softplus(xd[:, :57] @ W_dt^T + b_dt), both dirs in one launch
    gemm_tc<2, false><<<dim3(CDIV(DINNER, 128), MT, 2), 256>>>(
        (const float*)pxd0, (const float*)pxd1, DXP, W_dt, DTRANK, b_dt, nullptr,
        (float*)pd0, (float*)pd1, DINNER, MROWS, DINNER, DTRANK, 1);

    // 7. selective scan, both directions
    scan_kernel<<<2 * BSZ * 15, 128>>>(A_log, Dv);

    // 8. combine with gate
    combine_kernel<<<CDIV((long)MROWS * DINNER, 256), 256>>>();

    // 9. mamba_out = comb @ W_out^T  (reuse g_xn)
    gemm_tc<0, false><<<dim3(CDIV(DMODEL, 128), MT, 1), 256>>>(
        (const float*)pcomb, nullptr, DINNER, W_out, DINNER, nullptr, nullptr,
        (float*)pxn, nullptr, DMODEL, MROWS, DMODEL, DINNER, 1);

    // 10. out = rmsnorm(mamba_out + x, normf_w)
    rmsnorm_kernel<<<MROWS, 256>>>((const float*)pxn, (const float*)px,
                                   normf_w, out, DMODEL);
}